// round 5
// baseline (speedup 1.0000x reference)
#include <cuda_runtime.h>
#include <cuda_bf16.h>

// ---------------- problem constants ----------------
#define Bn 16
#define An 3
#define Cn 80
#define Hn 76
#define Wn 76
#define Tn 50
#define NCH 85               // 5 + C
#define HW  (Hn * Wn)        // 5776 (divisible by 4)
#define HW4 (HW / 4)         // 1444
#define Ntot (Bn * An * HW)  // 277248
#define Nvec (Bn * An * HW4) // 69312 float4 elements
#define NREC (Bn * Tn)       // 800
#define CONF_BLOCKS ((Nvec + 255) / 256)   // 271
#define REC_BLOCKS  Bn                     // 16 (one per batch)
#define TOT_BLOCKS  (CONF_BLOCKS + REC_BLOCKS)  // 287

// anchors / stride=8
__device__ __constant__ float c_aw[3] = {1.25f, 2.0f, 4.125f};
__device__ __constant__ float c_ah[3] = {1.625f, 3.75f, 2.875f};

// ---------------- device scratch (static zero-init; finalize re-zeroes) ----------------
__device__ double   g_sums[9];   // x, y, w, h, conf_obj, conf_noobj, cls, n_m, n_nm
__device__ unsigned g_done;      // finalize ticket

// softplus(p) = -log(1 - sigmoid(p)) = -log(sigmoid(-p)); fp32-accurate in data range
__device__ __forceinline__ float sp(float x) {
    return x > 0.f ? x + log1pf(expf(-x)) : log1pf(expf(x));
}
// clipped per reference (clip(log, -100))
__device__ __forceinline__ float spc(float x) { return fminf(sp(x), 100.f); }

// block-reduce two doubles into g_sums[i1], g_sums[i2] (thread 0 issues atomics)
__device__ __forceinline__ void block_reduce2(double v1, double v2, int i1, int i2) {
    __shared__ double s1[8], s2[8];
    int lane = threadIdx.x & 31, warp = threadIdx.x >> 5;
    #pragma unroll
    for (int o = 16; o > 0; o >>= 1) {
        v1 += __shfl_down_sync(0xffffffffu, v1, o);
        v2 += __shfl_down_sync(0xffffffffu, v2, o);
    }
    if (lane == 0) { s1[warp] = v1; s2[warp] = v2; }
    __syncthreads();
    if (warp == 0) {
        v1 = (lane < 8) ? s1[lane] : 0.0;
        v2 = (lane < 8) ? s2[lane] : 0.0;
        #pragma unroll
        for (int o = 4; o > 0; o >>= 1) {
            v1 += __shfl_down_sync(0xffffffffu, v1, o);
            v2 += __shfl_down_sync(0xffffffffu, v2, o);
        }
        if (lane == 0) {
            atomicAdd(&g_sums[i1], v1);
            atomicAdd(&g_sums[i2], v2);
        }
    }
}

// ---------------- single fused kernel ----------------
__global__ void yolo_loss_kernel(const float* __restrict__ inp,
                                 const float* __restrict__ tg,
                                 float* __restrict__ out) {
    int tid = threadIdx.x;

    if (blockIdx.x < CONF_BLOCKS) {
        // ---- conf pass: this block covers linear cells [cellBase, cellBase+1024) ----
        __shared__ unsigned sbits[32];     // bit set => noobj cleared (iou > 0.5)
        if (tid < 32) sbits[tid] = 0u;
        __syncthreads();

        int cellBase = blockIdx.x * 1024;
        // recompute noobj bits for this range from targets (L2-resident, ~3/thread)
        for (int r = tid; r < NREC; r += 256) {
            const float* p = tg + r * 5;
            float tc = p[0], xx = p[1], yy = p[2], ww = p[3], hh = p[4];
            if ((tc + xx + yy + ww + hh) == 0.0f) continue;   // invalid
            int b = r / Tn;
            float gw = ww * (float)Wn, gh = hh * (float)Hn;
            int gi = (int)(xx * (float)Wn), gj = (int)(yy * (float)Hn);
            float a1 = (gw + 1.f) * (gh + 1.f);
            #pragma unroll
            for (int a = 0; a < An; ++a) {
                float aw = c_aw[a], ah = c_ah[a];
                float inter = fmaxf(fminf(gw, aw) + 1.f, 0.f) * fmaxf(fminf(gh, ah) + 1.f, 0.f);
                float iou = inter / (a1 + (aw + 1.f) * (ah + 1.f) - inter + 1e-16f);
                if (iou > 0.5f) {
                    int idx = ((b * An + a) * Hn + gj) * Wn + gi;  // < Ntot by construction
                    if (idx >= cellBase && idx < cellBase + 1024) {
                        int loc = idx - cellBase;
                        atomicOr(&sbits[loc >> 5], 1u << (loc & 31));
                    }
                }
            }
        }
        __syncthreads();

        int v4 = blockIdx.x * 256 + tid;       // float4 index over (b,a,HW/4)
        double vsum = 0.0, cnt = 0.0;
        if (v4 < Nvec) {
            int plane = v4 / HW4;              // b*A + a
            int rem4 = v4 - plane * HW4;
            int b = plane / An, a = plane - b * An;
            int off4 = ((b * (An * NCH) + a * NCH + 4) * HW) / 4 + rem4;
            int loc = tid * 4;                 // local cell index of elem 0 (mult of 4, in-word)
            unsigned bits = sbits[loc >> 5] >> (loc & 31);
            float4 p = reinterpret_cast<const float4*>(inp)[off4];
            float f0 = (bits & 1u)        ? 0.f : spc(p.x);
            float f1 = ((bits >> 1) & 1u) ? 0.f : spc(p.y);
            float f2 = ((bits >> 2) & 1u) ? 0.f : spc(p.z);
            float f3 = ((bits >> 3) & 1u) ? 0.f : spc(p.w);
            int nset = (bits & 1u) + ((bits >> 1) & 1u) + ((bits >> 2) & 1u) + ((bits >> 3) & 1u);
            vsum = (double)(f0 + f1 + f2 + f3);
            cnt  = (double)(4 - nset);
        }
        block_reduce2(vsum, cnt, 5, 8);        // uniform call, internal barriers safe
    } else {
        // ---- record pass: one block per batch b; threads 0..49 build records in shared ----
        int b = blockIdx.x - CONF_BLOCKS;
        __shared__ int   s_ok[Tn], s_cell[Tn], s_a[Tn], s_rem[Tn], s_cls[Tn];
        __shared__ float s_tx[Tn], s_ty[Tn], s_tw[Tn], s_th[Tn];

        if (tid < Tn) {
            const float* p = tg + (b * Tn + tid) * 5;
            float tc = p[0], xx = p[1], yy = p[2], ww = p[3], hh = p[4];
            bool valid = ((tc + xx + yy + ww + hh) != 0.0f);
            float gx = xx * (float)Wn, gy = yy * (float)Hn;
            float gw = ww * (float)Wn, gh = hh * (float)Hn;
            int gi = (int)gx, gj = (int)gy;
            bool ok = valid && (gj < Hn) && (gi < Wn);

            float a1 = (gw + 1.f) * (gh + 1.f);
            int best = 0;
            float bestiou = -1.f;
            #pragma unroll
            for (int a = 0; a < An; ++a) {
                float aw = c_aw[a], ah = c_ah[a];
                float inter = fmaxf(fminf(gw, aw) + 1.f, 0.f) * fmaxf(fminf(gh, ah) + 1.f, 0.f);
                float iou = inter / (a1 + (aw + 1.f) * (ah + 1.f) - inter + 1e-16f);
                if (iou > bestiou) { bestiou = iou; best = a; }
            }
            s_ok[tid]   = ok ? 1 : 0;
            s_cell[tid] = ((b * An + best) * Hn + gj) * Wn + gi;
            s_a[tid]    = best;
            s_rem[tid]  = gj * Wn + gi;
            s_cls[tid]  = (int)tc;
            s_tx[tid]   = gx - (float)gi;
            s_ty[tid]   = gy - (float)gj;
            s_tw[tid]   = logf(gw / c_aw[best] + 1e-16f);
            s_th[tid]   = logf(gh / c_ah[best] + 1e-16f);
        }
        __syncthreads();

        int warp = tid >> 5, lane = tid & 31;
        bool did = false;
        for (int t = warp; t < Tn; t += 8) {        // no barriers inside loop
            if (!s_ok[t]) continue;
            int cell = s_cell[t], aa = s_a[t], rem = s_rem[t], clsI = s_cls[t];

            // last-wins: a later ok record with same scatter cell overrides this one
            bool winner = true;
            for (int t2 = t + 1; t2 < Tn; ++t2)
                if (s_ok[t2] && s_cell[t2] == cell) { winner = false; break; }

            int base = (b * (An * NCH) + aa * NCH) * HW + rem;

            if (winner) {
                // class baseline: sum_c softplus(p_c) (tcls = 0 baseline)
                float csum = 0.f;
                for (int c = lane; c < Cn; c += 32)
                    csum += spc(inp[base + (5 + c) * HW]);
                #pragma unroll
                for (int o = 16; o > 0; o >>= 1)
                    csum += __shfl_down_sync(0xffffffffu, csum, o);
                if (lane == 0) {
                    float p0 = inp[base];
                    float p1 = inp[base + HW];
                    float p2 = inp[base + 2 * HW];
                    float p3 = inp[base + 3 * HW];
                    float p4 = inp[base + 4 * HW];
                    float tx = s_tx[t], ty = s_ty[t], tw = s_tw[t], th = s_th[t];
                    atomicAdd(&g_sums[0], (double)(tx * spc(-p0) + (1.f - tx) * spc(p0)));
                    atomicAdd(&g_sums[1], (double)(ty * spc(-p1) + (1.f - ty) * spc(p1)));
                    atomicAdd(&g_sums[2], (double)((p2 - tw) * (p2 - tw)));
                    atomicAdd(&g_sums[3], (double)((p3 - th) * (p3 - th)));
                    atomicAdd(&g_sums[4], (double)spc(-p4));   // bce(conf, 1)
                    atomicAdd(&g_sums[6], (double)csum);
                    atomicAdd(&g_sums[7], 1.0);
                    did = true;
                }
            }

            // class one-hot delta; set semantics: first ok record with (cell, cls) wins
            bool firstcls = true;
            for (int t2 = 0; t2 < t; ++t2)
                if (s_ok[t2] && s_cell[t2] == cell && s_cls[t2] == clsI) { firstcls = false; break; }
            if (firstcls && lane == 0) {
                float pc = inp[base + (5 + clsI) * HW];
                atomicAdd(&g_sums[6], (double)(spc(-pc) - spc(pc)));
                did = true;
            }
        }
        if (did) __threadfence();
    }

    // ---------------- fused finalize: last block computes outputs, then resets state ----------------
    __syncthreads();
    if (tid == 0) {
        __threadfence();
        unsigned ticket = atomicAdd(&g_done, 1u);
        if (ticket == (unsigned)(TOT_BLOCKS - 1)) {
            __threadfence();
            volatile double* s = g_sums;
            double Nd = (double)Ntot;
            double nm = s[7], nnm = s[8];
            double lx = s[0] / Nd / nm;
            double ly = s[1] / Nd / nm;
            double lw = s[2] / Nd / nm;
            double lh = s[3] / Nd / nm;
            double lconf = s[4] / Nd / nm + 0.5 * s[5] / Nd / nnm;
            double lcls = s[6] / (nm * (double)Cn) / nm;
            double loss = 2.5 * (lx + ly) + 2.5 * (lw + lh) + lconf + lcls;
            out[0] = (float)loss;
            out[1] = (float)lx;
            out[2] = (float)ly;
            out[3] = (float)lw;
            out[4] = (float)lh;
            out[5] = (float)lconf;
            out[6] = (float)lcls;
            // reset for next invocation (graph replay determinism)
            #pragma unroll
            for (int i = 0; i < 9; ++i) g_sums[i] = 0.0;
            __threadfence();
            g_done = 0u;
        }
    }
}

extern "C" void kernel_launch(void* const* d_in, const int* in_sizes, int n_in,
                              void* d_out, int out_size) {
    const float* inp = (const float*)d_in[0];   // (B, A*85, H, W) fp32
    const float* tg  = (const float*)d_in[1];   // (B, T, 5) fp32
    float* out = (float*)d_out;
    yolo_loss_kernel<<<TOT_BLOCKS, 256>>>(inp, tg, out);
}

// round 11
// speedup vs baseline: 1.9022x; 1.9022x over previous
#include <cuda_runtime.h>
#include <cuda_bf16.h>

// ---------------- problem constants ----------------
#define Bn 16
#define An 3
#define Cn 80
#define Hn 76
#define Wn 76
#define Tn 50
#define NCH 85                 // 5 + C
#define HW  (Hn * Wn)          // 5776 (divisible by 4)
#define HW4 (HW / 4)           // 1444
#define Ntot (Bn * An * HW)    // 277248
#define Nvec (Bn * An * HW4)   // 69312 float4 elements
#define NCAND (Tn * An)        // 150 noobj candidates per batch
#define THREADS 512
#define CONF_BLOCKS ((Nvec + THREADS - 1) / THREADS)   // 136
#define REC_BLOCKS  (Bn * 2)                           // 32 (two per batch)
#define TOT_BLOCKS  (CONF_BLOCKS + REC_BLOCKS)         // 168

// anchors / stride=8
__device__ __constant__ float c_aw[3] = {1.25f, 2.0f, 4.125f};
__device__ __constant__ float c_ah[3] = {1.625f, 3.75f, 2.875f};

// ---------------- device scratch (static zero-init; finalize re-zeroes) ----------------
// x, y, w, h, conf_obj, conf_noobj_sum, cls, n_m, neg_cleared_count
__device__ double   g_sums[9];
__device__ unsigned g_done;      // finalize ticket

// softplus(p) = -log(1 - sigmoid(p)) = -log(sigmoid(-p)); branch-free, fp32-accurate
__device__ __forceinline__ float sp(float x) {
    return fmaxf(x, 0.f) + log1pf(expf(-fabsf(x)));
}
// clipped per reference (clip(log, -100))
__device__ __forceinline__ float spc(float x) { return fminf(sp(x), 100.f); }

// ---------------- single fused kernel ----------------
__global__ void __launch_bounds__(THREADS)
yolo_loss_kernel(const float* __restrict__ inp,
                 const float* __restrict__ tg,
                 float* __restrict__ out) {
    int tid = threadIdx.x;
    int lane = tid & 31, warp = tid >> 5;

    if (blockIdx.x < CONF_BLOCKS) {
        // ---- conf pass: pure streaming softplus reduction over the conf channel ----
        int v4 = blockIdx.x * THREADS + tid;
        float local = 0.f;
        if (v4 < Nvec) {
            int plane = v4 / HW4;                  // b*A + a
            int rem4 = v4 - plane * HW4;
            float4 p = reinterpret_cast<const float4*>(inp)[plane * (NCH * HW4) + 4 * HW4 + rem4];
            local = spc(p.x) + spc(p.y) + spc(p.z) + spc(p.w);
        }
        // warp reduce (float), block reduce (double), one atomic per block
        #pragma unroll
        for (int o = 16; o > 0; o >>= 1)
            local += __shfl_down_sync(0xffffffffu, local, o);
        __shared__ double sred[16];
        if (lane == 0) sred[warp] = (double)local;
        __syncthreads();
        if (warp == 0) {
            double v = (lane < 16) ? sred[lane] : 0.0;
            #pragma unroll
            for (int o = 8; o > 0; o >>= 1)
                v += __shfl_down_sync(0xffffffffu, v, o);
            if (lane == 0) atomicAdd(&g_sums[5], v);
        }
    } else {
        // ---- record pass: two blocks per batch ----
        int rb = blockIdx.x - CONF_BLOCKS;
        int b = rb >> 1, half = rb & 1;
        __shared__ int   s_ok[Tn], s_cell[Tn], s_a[Tn], s_rem[Tn], s_cls[Tn];
        __shared__ float s_tx[Tn], s_ty[Tn], s_tw[Tn], s_th[Tn];
        __shared__ int   s_nm[NCAND];   // linear cell idx of iou>0.5 candidate, or -1

        // phase A: threads 0..49 build this batch's records (both blocks duplicate this)
        if (tid < Tn) {
            const float* p = tg + (b * Tn + tid) * 5;
            float tc = p[0], xx = p[1], yy = p[2], ww = p[3], hh = p[4];
            bool valid = ((tc + xx + yy + ww + hh) != 0.0f);
            float gx = xx * (float)Wn, gy = yy * (float)Hn;
            float gw = ww * (float)Wn, gh = hh * (float)Hn;
            int gi = (int)gx, gj = (int)gy;
            bool ok = valid && (gj < Hn) && (gi < Wn);

            float a1 = (gw + 1.f) * (gh + 1.f);
            int best = 0;
            float bestiou = -1.f;
            #pragma unroll
            for (int a = 0; a < An; ++a) {
                float aw = c_aw[a], ah = c_ah[a];
                float inter = fmaxf(fminf(gw, aw) + 1.f, 0.f) * fmaxf(fminf(gh, ah) + 1.f, 0.f);
                float iou = inter / (a1 + (aw + 1.f) * (ah + 1.f) - inter + 1e-16f);
                if (iou > bestiou) { bestiou = iou; best = a; }
                // noobj candidate: valid & iou>0.5, dropped only if flat idx OOB (ref semantics)
                long idx = (long)((b * An + a) * Hn + gj) * Wn + gi;
                s_nm[tid * An + a] = (valid && iou > 0.5f && idx >= 0 && idx < Ntot)
                                     ? (int)idx : -1;
            }
            s_ok[tid]   = ok ? 1 : 0;
            s_cell[tid] = ((b * An + best) * Hn + gj) * Wn + gi;
            s_a[tid]    = best;
            s_rem[tid]  = gj * Wn + gi;
            s_cls[tid]  = (int)tc;
            s_tx[tid]   = gx - (float)gi;
            s_ty[tid]   = gy - (float)gj;
            s_tw[tid]   = logf(gw / c_aw[best] + 1e-16f);
            s_th[tid]   = logf(gh / c_ah[best] + 1e-16f);
        }
        __syncthreads();

        bool did = false;

        // phase B: this block owns records t with (t & 1) == half; 25 records / 16 warps
        for (int ridx = warp; ridx < 25; ridx += 16) {
            int t = 2 * ridx + half;
            if (!s_ok[t]) continue;
            int cell = s_cell[t], aa = s_a[t], rem = s_rem[t], clsI = s_cls[t];

            // last-wins: a later ok record (any parity) with same scatter cell overrides
            bool winner = true;
            for (int t2 = t + 1; t2 < Tn; ++t2)
                if (s_ok[t2] && s_cell[t2] == cell) { winner = false; break; }

            int base = (b * (An * NCH) + aa * NCH) * HW + rem;

            if (winner) {
                // class baseline: sum_c softplus(p_c) (tcls = 0 baseline)
                float csum = 0.f;
                for (int c = lane; c < Cn; c += 32)
                    csum += spc(inp[base + (5 + c) * HW]);
                #pragma unroll
                for (int o = 16; o > 0; o >>= 1)
                    csum += __shfl_down_sync(0xffffffffu, csum, o);
                if (lane == 0) {
                    float p0 = inp[base];
                    float p1 = inp[base + HW];
                    float p2 = inp[base + 2 * HW];
                    float p3 = inp[base + 3 * HW];
                    float p4 = inp[base + 4 * HW];
                    float tx = s_tx[t], ty = s_ty[t], tw = s_tw[t], th = s_th[t];
                    atomicAdd(&g_sums[0], (double)(tx * spc(-p0) + (1.f - tx) * spc(p0)));
                    atomicAdd(&g_sums[1], (double)(ty * spc(-p1) + (1.f - ty) * spc(p1)));
                    atomicAdd(&g_sums[2], (double)((p2 - tw) * (p2 - tw)));
                    atomicAdd(&g_sums[3], (double)((p3 - th) * (p3 - th)));
                    atomicAdd(&g_sums[4], (double)spc(-p4));   // bce(conf, 1)
                    atomicAdd(&g_sums[6], (double)csum);
                    atomicAdd(&g_sums[7], 1.0);
                    did = true;
                }
            }

            // class one-hot delta; set semantics: first ok record with (cell, cls) wins
            bool firstcls = true;
            for (int t2 = 0; t2 < t; ++t2)
                if (s_ok[t2] && s_cell[t2] == cell && s_cls[t2] == clsI) { firstcls = false; break; }
            if (firstcls && lane == 0) {
                float pc = inp[base + (5 + clsI) * HW];
                atomicAdd(&g_sums[6], (double)(spc(-pc) - spc(pc)));
                did = true;
            }
        }

        // phase C: noobj corrections — subtract softplus at distinct iou>0.5 cells.
        // candidate k owned by block (k & 1 == half); "first k with this cell" counts.
        if (tid < (NCAND / 2)) {
            int k = 2 * tid + half;
            int cell = s_nm[k];
            if (cell >= 0) {
                bool first = true;
                for (int k2 = 0; k2 < k; ++k2)
                    if (s_nm[k2] == cell) { first = false; break; }
                if (first) {
                    int plane = cell / HW;
                    int hw = cell - plane * HW;
                    float p = inp[plane * (NCH * HW) + 4 * HW + hw];
                    atomicAdd(&g_sums[5], -(double)spc(p));
                    atomicAdd(&g_sums[8], -1.0);
                    did = true;
                }
            }
        }
        if (did) __threadfence();
    }

    // ---------------- fused finalize: last block computes outputs, resets state ----------------
    __syncthreads();
    if (tid == 0) {
        __threadfence();
        unsigned ticket = atomicAdd(&g_done, 1u);
        if (ticket == (unsigned)(TOT_BLOCKS - 1)) {
            __threadfence();
            volatile double* s = g_sums;
            double Nd = (double)Ntot;
            double nm = s[7];
            double nnm = Nd + s[8];          // Ntot - #distinct cleared cells
            double lx = s[0] / Nd / nm;
            double ly = s[1] / Nd / nm;
            double lw = s[2] / Nd / nm;
            double lh = s[3] / Nd / nm;
            double lconf = s[4] / Nd / nm + 0.5 * s[5] / Nd / nnm;
            double lcls = s[6] / (nm * (double)Cn) / nm;
            double loss = 2.5 * (lx + ly) + 2.5 * (lw + lh) + lconf + lcls;
            out[0] = (float)loss;
            out[1] = (float)lx;
            out[2] = (float)ly;
            out[3] = (float)lw;
            out[4] = (float)lh;
            out[5] = (float)lconf;
            out[6] = (float)lcls;
            // reset for next invocation (graph replay determinism)
            #pragma unroll
            for (int i = 0; i < 9; ++i) g_sums[i] = 0.0;
            __threadfence();
            g_done = 0u;
        }
    }
}

extern "C" void kernel_launch(void* const* d_in, const int* in_sizes, int n_in,
                              void* d_out, int out_size) {
    const float* inp = (const float*)d_in[0];   // (B, A*85, H, W) fp32
    const float* tg  = (const float*)d_in[1];   // (B, T, 5) fp32
    float* out = (float*)d_out;
    yolo_loss_kernel<<<TOT_BLOCKS, THREADS>>>(inp, tg, out);
}